// round 1
// baseline (speedup 1.0000x reference)
#include <cuda_runtime.h>
#include <float.h>

#define BATCH 32
#define HH 1024
#define WW 1024
#define TOPK 200
#define CAND_MAX 65536
#define TILE 32

// per-image candidate compaction buffers (static device scratch — no allocs)
__device__ int d_count[BATCH];
__device__ unsigned long long d_cand[BATCH][CAND_MAX];

__global__ void zero_counts_kernel() {
    if (threadIdx.x < BATCH) d_count[threadIdx.x] = 0;
}

// Fused 7x7 max-pool NMS. Block = 32x32 output tile, 256 threads.
__global__ void nms_kernel(const float* __restrict__ in) {
    const int img = blockIdx.z;
    const int tx0 = blockIdx.x * TILE;
    const int ty0 = blockIdx.y * TILE;

    __shared__ float s[TILE + 6][TILE + 6 + 2];   // 38 x 40 (padded)
    __shared__ float hmax[TILE + 6][TILE];        // 38 x 32

    const float* base = in + (size_t)img * HH * WW;
    const int tid = threadIdx.x;

    // load 38x38 halo tile (pad -FLT_MAX == torch maxpool -inf padding)
    for (int i = tid; i < 38 * 38; i += 256) {
        int r = i / 38, c = i % 38;
        int gy = ty0 + r - 3;
        int gx = tx0 + c - 3;
        float v = -FLT_MAX;
        if ((unsigned)gy < HH && (unsigned)gx < WW)
            v = base[(size_t)gy * WW + gx];
        s[r][c] = v;
    }
    __syncthreads();

    // horizontal 7-max: 38 rows x 32 output cols
    for (int i = tid; i < 38 * 32; i += 256) {
        int r = i / 32, c = i % 32;
        float m = s[r][c];
        #pragma unroll
        for (int k = 1; k < 7; k++) m = fmaxf(m, s[r][c + k]);
        hmax[r][c] = m;
    }
    __syncthreads();

    // vertical 7-max + peak test: 32x32 outputs
    for (int i = tid; i < 32 * 32; i += 256) {
        int r = i / 32, c = i % 32;
        float m = hmax[r][c];
        #pragma unroll
        for (int k = 1; k < 7; k++) m = fmaxf(m, hmax[r + k][c]);
        float center = s[r + 3][c + 3];
        // pooled == center  <=>  center is window max (exact: same fmaxf chain values)
        if (center > 0.1f && m == center) {
            unsigned gy = ty0 + r;
            unsigned gx = tx0 + c;
            unsigned idx = gy * WW + gx;
            // key: descending value, then ascending index (matches lax.top_k ties)
            unsigned long long key =
                ((unsigned long long)__float_as_uint(center) << 32) |
                (unsigned long long)(0xFFFFFFFFu - idx);
            int slot = atomicAdd(&d_count[img], 1);
            if (slot < CAND_MAX) d_cand[img][slot] = key;
        }
    }
}

// One block per image, 1024 threads: radix-select cutoff on value bits,
// collect survivors into shared buffer, bitonic sort, emit top-200.
__global__ void __launch_bounds__(1024) topk_kernel(float* __restrict__ out) {
    const int img = blockIdx.x;
    const int tid = threadIdx.x;
    int n = d_count[img];
    if (n > CAND_MAX) n = CAND_MAX;
    const unsigned long long* cand = d_cand[img];

    __shared__ unsigned hist[256];
    __shared__ unsigned s_above, s_digit, s_total;
    __shared__ unsigned long long buf[1024];
    __shared__ int s_cnt;

    unsigned prefix = 0;
    unsigned above = 0;
    int shift = 24;
    bool done = false;

    for (int lev = 0; lev < 4 && !done; lev++) {
        shift = 24 - lev * 8;
        for (int i = tid; i < 256; i += 1024) hist[i] = 0;
        __syncthreads();
        for (int i = tid; i < n; i += 1024) {
            unsigned vb = (unsigned)(cand[i] >> 32);
            bool in = (lev == 0) || ((vb >> (shift + 8)) == prefix);
            if (in) atomicAdd(&hist[(vb >> shift) & 0xFFu], 1u);
        }
        __syncthreads();
        if (tid == 0) {
            unsigned cum = 0;
            int d = 0;
            for (int b = 255; b >= 0; b--) {
                if (above + cum + hist[b] >= TOPK || b == 0) { d = b; break; }
                cum += hist[b];
            }
            s_above = above + cum;
            s_digit = (unsigned)d;
            s_total = above + cum + hist[d];
        }
        __syncthreads();
        above = s_above;
        prefix = (prefix << 8) | s_digit;
        unsigned total_ge = s_total;
        __syncthreads();
        if (total_ge <= 1024) done = true;  // survivors fit the sort buffer
    }

    // collect all candidates with value-bits prefix >= cutoff
    if (tid == 0) s_cnt = 0;
    __syncthreads();
    for (int i = tid; i < n; i += 1024) {
        unsigned long long k = cand[i];
        unsigned vb = (unsigned)(k >> 32);
        if ((vb >> shift) >= prefix) {
            int p = atomicAdd(&s_cnt, 1);
            if (p < 1024) buf[p] = k;
        }
    }
    __syncthreads();
    int m = s_cnt < 1024 ? s_cnt : 1024;
    for (int i = tid; i < 1024; i += 1024)
        if (i >= m) buf[i] = 0ull;
    __syncthreads();

    // bitonic sort 1024 keys, descending
    for (int k = 2; k <= 1024; k <<= 1) {
        for (int j = k >> 1; j > 0; j >>= 1) {
            int i = tid;
            int ixj = i ^ j;
            if (ixj > i) {
                unsigned long long a = buf[i], b = buf[ixj];
                bool swap = ((i & k) == 0) ? (a < b) : (a > b);
                if (swap) { buf[i] = b; buf[ixj] = a; }
            }
            __syncthreads();
        }
    }

    // emit: coords [B, K, 2] (row, col) then probs [B, K], all fp32
    float* coords = out;                                 // BATCH*TOPK*2
    float* probs  = out + (size_t)BATCH * TOPK * 2;      // BATCH*TOPK
    if (tid < TOPK) {
        unsigned long long key = buf[tid];
        float prob;
        unsigned row, col;
        if (key == 0ull) {
            prob = 0.0f; row = 0; col = 0;
        } else {
            prob = __uint_as_float((unsigned)(key >> 32));
            unsigned idx = 0xFFFFFFFFu - (unsigned)(key & 0xFFFFFFFFull);
            row = idx / WW;
            col = idx % WW;
        }
        size_t o = (size_t)img * TOPK + tid;
        coords[o * 2 + 0] = (float)row;
        coords[o * 2 + 1] = (float)col;
        probs[o] = prob;
    }
}

extern "C" void kernel_launch(void* const* d_in, const int* in_sizes, int n_in,
                              void* d_out, int out_size) {
    const float* in = (const float*)d_in[0];
    float* out = (float*)d_out;

    zero_counts_kernel<<<1, 32>>>();
    dim3 grid(WW / TILE, HH / TILE, BATCH);
    nms_kernel<<<grid, 256>>>(in);
    topk_kernel<<<BATCH, 1024>>>(out);
}